// round 5
// baseline (speedup 1.0000x reference)
#include <cuda_runtime.h>
#include <cuda_bf16.h>

// HintGenKernelBatched: masked XOR-parity gather-reduce.
//
// Confirmed world (R2-R4 evidence):
//   entries:        [1000000, 5]  int32 (JAX x64 disabled demotes int64->int32)
//   padded_indices: [4096, 2048]  int32, values in [0, 1e6)
//   valid_mask:     [4096, 2048]  int32, values in {0, 1}
//   out:            [4096, 5]     FLOAT32  (harness __output__ dtype; raw int
//                                 bit-stores produced sNaN patterns -> the
//                                 observed "invalid value in cast" + nan)
//
// Parity is computed exactly in 32-bit integer registers, then converted
// numerically to float32 on store. All inputs have bit31 == 0, so every XOR
// result is a nonnegative int < 2^31; float32 conversion rel-err ~1e-7.
//
// One CTA per hint. Indices/mask streamed coalesced as int4; entry-row
// gathers predicated on mask (Bernoulli(1/2) -> halves gather traffic);
// warp-shuffle + smem XOR tree reduction.

#define MAX_SUBSET 2048
#define ROW 5
#define THREADS 256

__global__ __launch_bounds__(THREADS, 8) void hint_parity_kernel(
    const int* __restrict__ entries,
    const int* __restrict__ padded_indices,
    const int* __restrict__ valid_mask,
    float* __restrict__ out)
{
    const int h = blockIdx.x;
    const int t = threadIdx.x;
    const size_t base = (size_t)h * MAX_SUBSET;

    const int4* __restrict__ idx4 = reinterpret_cast<const int4*>(padded_indices + base);
    const int4* __restrict__ msk4 = reinterpret_cast<const int4*>(valid_mask + base);

    unsigned a0 = 0, a1 = 0, a2 = 0, a3 = 0, a4 = 0;

    // 2048 slots / (256 threads * 4 per int4) = 2 passes
    #pragma unroll
    for (int p = 0; p < MAX_SUBSET / (THREADS * 4); ++p) {
        const int4 iv = idx4[p * THREADS + t];
        const int4 mv = msk4[p * THREADS + t];

        // Predicated gather of one 5-int row: issue all 5 loads, then fold.
        #define GATHER(I, M)                                               \
            if (M) {                                                       \
                const int* __restrict__ e = entries + (size_t)(unsigned)(I) * ROW; \
                const unsigned v0 = (unsigned)__ldg(e + 0);                \
                const unsigned v1 = (unsigned)__ldg(e + 1);                \
                const unsigned v2 = (unsigned)__ldg(e + 2);                \
                const unsigned v3 = (unsigned)__ldg(e + 3);                \
                const unsigned v4 = (unsigned)__ldg(e + 4);                \
                a0 ^= v0; a1 ^= v1; a2 ^= v2; a3 ^= v3; a4 ^= v4;          \
            }

        GATHER(iv.x, mv.x)
        GATHER(iv.y, mv.y)
        GATHER(iv.z, mv.z)
        GATHER(iv.w, mv.w)
        #undef GATHER
    }

    // Intra-warp XOR reduction
    #pragma unroll
    for (int o = 16; o > 0; o >>= 1) {
        a0 ^= __shfl_xor_sync(0xffffffffu, a0, o);
        a1 ^= __shfl_xor_sync(0xffffffffu, a1, o);
        a2 ^= __shfl_xor_sync(0xffffffffu, a2, o);
        a3 ^= __shfl_xor_sync(0xffffffffu, a3, o);
        a4 ^= __shfl_xor_sync(0xffffffffu, a4, o);
    }

    // Cross-warp reduction (8 warps)
    __shared__ unsigned red[THREADS / 32][ROW];
    const int warp = t >> 5;
    const int lane = t & 31;
    if (lane == 0) {
        red[warp][0] = a0;
        red[warp][1] = a1;
        red[warp][2] = a2;
        red[warp][3] = a3;
        red[warp][4] = a4;
    }
    __syncthreads();

    if (t < ROW) {
        unsigned v = red[0][t];
        #pragma unroll
        for (int w = 1; w < THREADS / 32; ++w) v ^= red[w][t];
        // NUMERIC conversion to float32 (values < 2^31, nonnegative).
        out[(size_t)h * ROW + t] = (float)v;
    }
}

extern "C" void kernel_launch(void* const* d_in, const int* in_sizes, int n_in,
                              void* d_out, int out_size)
{
    const int* entries        = (const int*)d_in[0];
    const int* padded_indices = (const int*)d_in[1];
    const int* valid_mask     = (const int*)d_in[2];
    float* out = (float*)d_out;

    const int num_hints = out_size / ROW;  // 4096 (out_size in output elements)
    hint_parity_kernel<<<num_hints, THREADS>>>(entries, padded_indices, valid_mask, out);
}

// round 6
// speedup vs baseline: 1.3135x; 1.3135x over previous
#include <cuda_runtime.h>
#include <cuda_bf16.h>

// HintGenKernelBatched: masked XOR-parity gather-reduce.
//   entries:        [1000000, 5]  int32
//   padded_indices: [4096, 2048]  int32 in [0, 1e6)
//   valid_mask:     [4096, 2048]  int32 in {0, 1}
//   out:            [4096, 5]     float32 (numeric convert; values < 2^31)
//
// R5 profile: L1tex 82% (top), L2 51%, DRAM 25%, issue 14% -> L1-wavefront
// bound. Per-lane scalar gathers cost ~5 wavefronts/row. This version gathers
// COOPERATIVELY: one 8-lane group per row, lane j<5 loads word j, so one LDG
// wavefront delivers a whole 20B row (~1.16 wf/row incl. line crossings).
//
// Phase 1: stage masked indices (-1 = skip) into smem, coalesced int4.
// Phase 2: 32 groups/CTA sweep the 2048 slots; predicated row gathers.
// Reduce:  shfl_xor(8), shfl_xor(16) folds the 4 groups/warp; smem folds warps.

#define MAX_SUBSET 2048
#define ROW 5
#define THREADS 256
#define NGROUPS (THREADS / 8)   // 32 row-gather groups per CTA

__global__ __launch_bounds__(THREADS, 8) void hint_parity_kernel(
    const int* __restrict__ entries,
    const int* __restrict__ padded_indices,
    const int* __restrict__ valid_mask,
    float* __restrict__ out)
{
    __shared__ int4 sidx4[MAX_SUBSET / 4];          // masked indices, -1 = invalid
    __shared__ unsigned red[THREADS / 32][ROW];

    const int h = blockIdx.x;
    const int t = threadIdx.x;
    const size_t base = (size_t)h * MAX_SUBSET;

    const int4* __restrict__ idx4 = reinterpret_cast<const int4*>(padded_indices + base);
    const int4* __restrict__ msk4 = reinterpret_cast<const int4*>(valid_mask + base);

    // ---- Phase 1: coalesced stream + mask fold into smem ----
    #pragma unroll
    for (int p = 0; p < MAX_SUBSET / (THREADS * 4); ++p) {
        const int4 iv = idx4[p * THREADS + t];
        const int4 mv = msk4[p * THREADS + t];
        int4 o;
        o.x = mv.x ? iv.x : -1;
        o.y = mv.y ? iv.y : -1;
        o.z = mv.z ? iv.z : -1;
        o.w = mv.w ? iv.w : -1;
        sidx4[p * THREADS + t] = o;                 // STS.128, conflict-free
    }
    __syncthreads();

    const int* __restrict__ sidx = reinterpret_cast<const int*>(sidx4);

    // ---- Phase 2: cooperative gather, one 8-lane group per row ----
    const int lane = t & 31;
    const int warp = t >> 5;
    const int g    = t >> 3;                        // group id 0..31
    const int j    = t & 7;                         // word-within-row (j<5 active)
    const bool wlane = (j < ROW);

    unsigned acc = 0;

    #pragma unroll 4
    for (int s = g; s < MAX_SUBSET; s += NGROUPS) {
        const int mi = sidx[s];                     // broadcast LDS per group
        if (wlane && mi >= 0) {
            acc ^= (unsigned)__ldg(entries + (size_t)(unsigned)mi * ROW + j);
        }
    }

    // ---- Reduce the 4 groups of each warp (lanes with equal t&7 combine) ----
    acc ^= __shfl_xor_sync(0xffffffffu, acc, 8);
    acc ^= __shfl_xor_sync(0xffffffffu, acc, 16);

    // lanes 0..4 of each warp now hold the warp's parity for words 0..4
    if (lane < ROW) red[warp][lane] = acc;
    __syncthreads();

    // ---- Fold 8 warps, store float32 ----
    if (t < ROW) {
        unsigned v = red[0][t];
        #pragma unroll
        for (int w = 1; w < THREADS / 32; ++w) v ^= red[w][t];
        out[(size_t)h * ROW + t] = (float)v;        // numeric convert, values < 2^31
    }
}

extern "C" void kernel_launch(void* const* d_in, const int* in_sizes, int n_in,
                              void* d_out, int out_size)
{
    const int* entries        = (const int*)d_in[0];
    const int* padded_indices = (const int*)d_in[1];
    const int* valid_mask     = (const int*)d_in[2];
    float* out = (float*)d_out;

    const int num_hints = out_size / ROW;  // 4096
    hint_parity_kernel<<<num_hints, THREADS>>>(entries, padded_indices, valid_mask, out);
}